// round 13
// baseline (speedup 1.0000x reference)
#include <cuda_runtime.h>
#include <math.h>
#include <stdint.h>

// Problem dims
#define B_ 128
#define S_ 128
#define H_ 1024
#define A_ 1024
#define V_ 50000

// ---------------- scratch (device globals: allocation-free) ----------------
__device__ float g_xbuf[B_ * H_];        // gathered embeddings x = emb[input]
__device__ float g_gates[B_ * 4 * H_];   // LSTM pre-activations
__device__ float g_avin[B_ * 2 * H_];    // [context | h]
__device__ float g_av[B_ * A_];          // attention_vector (post tanh)

// ---------------- packed f32x2 helpers ----------------
__device__ __forceinline__ unsigned long long pack2(float lo, float hi) {
    unsigned long long r;
    unsigned int a = __float_as_uint(lo), b = __float_as_uint(hi);
    asm("mov.b64 %0, {%1,%2};" : "=l"(r) : "r"(a), "r"(b));
    return r;
}
__device__ __forceinline__ void unpack2(unsigned long long v, float& lo, float& hi) {
    unsigned int a, b;
    asm("mov.b64 {%0,%1}, %2;" : "=r"(a), "=r"(b) : "l"(v));
    lo = __uint_as_float(a);
    hi = __uint_as_float(b);
}
__device__ __forceinline__ void ffma2(unsigned long long& d, unsigned long long a,
                                      unsigned long long b) {
    asm("fma.rn.f32x2 %0, %1, %2, %0;" : "+l"(d) : "l"(a), "l"(b));
}

// ---------------- generic SGEMM: C[M,N] = A[M,K] @ B[N,K]^T + bias ----------------
// Dual-source along K (for the [x|prev_h] @ [W_ih|W_hh]^T fused gates GEMM):
// for k < Ksplit use (A1,B1) at offset k, else (A2,B2) at offset k-Ksplit.
// ACT: 0 = none, 1 = tanh.
template <int BM, int BN, int TM, int TN, int ACT>
__global__ void __launch_bounds__(256) sgemm_f32x2(
    const float* __restrict__ A1, const float* __restrict__ A2, int lda,
    const float* __restrict__ B1, const float* __restrict__ B2, int ldb,
    const float* __restrict__ bias1, const float* __restrict__ bias2,
    float* __restrict__ C, int N, int K, int Ksplit)
{
    constexpr int BK  = 32;
    constexpr int TNX = BN / TN;   // threads along N
    constexpr int TNY = BM / TM;   // threads along M
    static_assert(TNX * TNY == 256, "thread tiling must cover 256 threads");
    static_assert((TN % 2) == 0, "TN must be even for f32x2 pairing");
    constexpr int A4 = (BM * BK) / (256 * 4);
    constexpr int B4 = (BN * BK) / (256 * 4);
    static_assert((BM * BK) % 1024 == 0 && (BN * BK) % 1024 == 0, "tile loader");

    __shared__ float As[BK][BM];
    __shared__ float Bs[BK][BN];

    const int tid = threadIdx.x;
    const int tx  = tid % TNX;
    const int ty  = tid / TNX;
    const int n0  = blockIdx.x * BN;
    const int m0  = blockIdx.y * BM;

    unsigned long long acc[TM][TN / 2];
#pragma unroll
    for (int i = 0; i < TM; i++)
#pragma unroll
        for (int j = 0; j < TN / 2; j++) acc[i][j] = 0ull;

    for (int k0 = 0; k0 < K; k0 += BK) {
        const float* Asrc;
        const float* Bsrc;
        int kk;
        if (k0 < Ksplit) { Asrc = A1; Bsrc = B1; kk = k0; }
        else             { Asrc = A2; Bsrc = B2; kk = k0 - Ksplit; }

        // load A tile (BM x 32), transposed into As[k][m]; all M rows valid
#pragma unroll
        for (int r = 0; r < A4; r++) {
            int f   = tid + r * 256;
            int row = f >> 3;       // 8 float4 per 32-col row
            int cv  = f & 7;
            float4 v = *(const float4*)(Asrc + (long long)(m0 + row) * lda + kk + cv * 4);
            As[cv * 4 + 0][row] = v.x;
            As[cv * 4 + 1][row] = v.y;
            As[cv * 4 + 2][row] = v.z;
            As[cv * 4 + 3][row] = v.w;
        }
        // load B tile (BN x 32) with N guard
#pragma unroll
        for (int r = 0; r < B4; r++) {
            int f   = tid + r * 256;
            int row = f >> 3;
            int cv  = f & 7;
            int g   = n0 + row;
            float4 v;
            if (g < N) v = *(const float4*)(Bsrc + (long long)g * ldb + kk + cv * 4);
            else       v = make_float4(0.f, 0.f, 0.f, 0.f);
            Bs[cv * 4 + 0][row] = v.x;
            Bs[cv * 4 + 1][row] = v.y;
            Bs[cv * 4 + 2][row] = v.z;
            Bs[cv * 4 + 3][row] = v.w;
        }
        __syncthreads();

#pragma unroll
        for (int k = 0; k < BK; k++) {
            float a[TM];
#pragma unroll
            for (int i = 0; i < TM; i++) a[i] = As[k][ty * TM + i];
            unsigned long long bp[TN / 2];
#pragma unroll
            for (int j = 0; j < TN / 2; j++)
                bp[j] = *(const unsigned long long*)&Bs[k][tx * TN + 2 * j];
#pragma unroll
            for (int i = 0; i < TM; i++) {
                unsigned long long ap = pack2(a[i], a[i]);
#pragma unroll
                for (int j = 0; j < TN / 2; j++) ffma2(acc[i][j], ap, bp[j]);
            }
        }
        __syncthreads();
    }

    // epilogue
#pragma unroll
    for (int i = 0; i < TM; i++) {
        int m = m0 + ty * TM + i;
#pragma unroll
        for (int j = 0; j < TN / 2; j++) {
            float c0, c1;
            unpack2(acc[i][j], c0, c1);
            int col = n0 + tx * TN + 2 * j;
            if (col < N) {
                float bb = bias1 ? bias1[col] : 0.f;
                if (bias2) bb += bias2[col];
                float v = c0 + bb;
                if (ACT == 1) v = tanhf(v);
                C[(long long)m * N + col] = v;
            }
            if (col + 1 < N) {
                float bb = bias1 ? bias1[col + 1] : 0.f;
                if (bias2) bb += bias2[col + 1];
                float v = c1 + bb;
                if (ACT == 1) v = tanhf(v);
                C[(long long)m * N + col + 1] = v;
            }
        }
    }
}

// ---------------- embedding gather: g_xbuf[b, :] = emb[input[b], :] ----------------
__global__ void gather_emb_kernel(const int* __restrict__ input,
                                  const float* __restrict__ emb) {
    int idx = blockIdx.x * blockDim.x + threadIdx.x;  // float4 index
    int b   = idx >> 8;                               // H_/4 = 256 float4/row
    int k4  = idx & 255;
    ((float4*)g_xbuf)[idx] =
        ((const float4*)(emb + (long long)input[b] * H_))[k4];
}

// ---------------- LSTM elementwise: c, h from gates ----------------
__global__ void lstm_cell_kernel(const float* __restrict__ prev_c,
                                 float* __restrict__ out) {
    int idx = blockIdx.x * blockDim.x + threadIdx.x;
    if (idx >= B_ * H_) return;
    int b = idx >> 10;
    int j = idx & 1023;
    const float* g = g_gates + b * (4 * H_);
    float ig = g[j];
    float fg = g[H_ + j];
    float gg = g[2 * H_ + j];
    float og = g[3 * H_ + j];
    float si = 1.f / (1.f + expf(-ig));
    float sf = 1.f / (1.f + expf(-fg));
    float so = 1.f / (1.f + expf(-og));
    float c  = sf * prev_c[idx] + si * tanhf(gg);
    float h  = so * tanhf(c);
    out[(long long)B_ * V_ + idx] = h;                 // h output section
    out[(long long)B_ * V_ + B_ * H_ + idx] = c;       // c output section
    g_avin[b * (2 * H_) + H_ + j] = h;                 // second half of [ctx|h]
}

// ---------------- dot attention + softmax + context (one block per batch) ----------
__global__ void __launch_bounds__(256) attention_kernel(const float* __restrict__ enc) {
    int b = blockIdx.x;
    __shared__ float sh[H_];
    __shared__ float sc[S_];
    __shared__ float sinv;
    int tid  = threadIdx.x;
    int lane = tid & 31;
    int w    = tid >> 5;

    for (int t = tid; t < H_; t += 256) sh[t] = g_avin[b * (2 * H_) + H_ + t];
    __syncthreads();

    const float* eb = enc + (long long)b * S_ * H_;
    for (int s = w; s < S_; s += 8) {
        const float* e = eb + s * H_;
        float a0 = 0.f, a1 = 0.f;
#pragma unroll 4
        for (int t = lane; t < H_; t += 64) {
            a0 += e[t] * sh[t];
            a1 += e[t + 32] * sh[t + 32];
        }
        float acc = a0 + a1;
#pragma unroll
        for (int o = 16; o; o >>= 1) acc += __shfl_xor_sync(0xffffffffu, acc, o);
        if (lane == 0) sc[s] = (acc == 0.f) ? -1e11f : acc;
    }
    __syncthreads();

    if (w == 0) {
        float v0 = sc[lane], v1 = sc[lane + 32], v2 = sc[lane + 64], v3 = sc[lane + 96];
        float m = fmaxf(fmaxf(v0, v1), fmaxf(v2, v3));
#pragma unroll
        for (int o = 16; o; o >>= 1) m = fmaxf(m, __shfl_xor_sync(0xffffffffu, m, o));
        float e0 = expf(v0 - m), e1 = expf(v1 - m), e2 = expf(v2 - m), e3 = expf(v3 - m);
        sc[lane] = e0; sc[lane + 32] = e1; sc[lane + 64] = e2; sc[lane + 96] = e3;
        float s4 = e0 + e1 + e2 + e3;
#pragma unroll
        for (int o = 16; o; o >>= 1) s4 += __shfl_xor_sync(0xffffffffu, s4, o);
        if (lane == 0) sinv = 1.f / s4;
    }
    __syncthreads();

    float inv = sinv;
    float acc0 = 0.f, acc1 = 0.f, acc2 = 0.f, acc3 = 0.f;
#pragma unroll 4
    for (int s = 0; s < S_; s++) {
        float a = sc[s];
        const float* e = eb + s * H_ + tid;
        acc0 += a * e[0];
        acc1 += a * e[256];
        acc2 += a * e[512];
        acc3 += a * e[768];
    }
    g_avin[b * (2 * H_) + tid]       = acc0 * inv;
    g_avin[b * (2 * H_) + tid + 256] = acc1 * inv;
    g_avin[b * (2 * H_) + tid + 512] = acc2 * inv;
    g_avin[b * (2 * H_) + tid + 768] = acc3 * inv;
}

// ---------------- log_softmax over V, in place (one block per row) ----------------
__global__ void __launch_bounds__(256) log_softmax_kernel(float* __restrict__ out) {
    int b = blockIdx.x;
    float* row = out + (long long)b * V_;
    __shared__ float sred[8];
    int tid  = threadIdx.x;
    int lane = tid & 31;
    int w    = tid >> 5;

    float m = -INFINITY;
    for (int t = tid; t < V_; t += 256) m = fmaxf(m, row[t]);
#pragma unroll
    for (int o = 16; o; o >>= 1) m = fmaxf(m, __shfl_xor_sync(0xffffffffu, m, o));
    if (lane == 0) sred[w] = m;
    __syncthreads();
    float bm = sred[0];
#pragma unroll
    for (int i = 1; i < 8; i++) bm = fmaxf(bm, sred[i]);
    __syncthreads();

    float s = 0.f;
    for (int t = tid; t < V_; t += 256) s += expf(row[t] - bm);
#pragma unroll
    for (int o = 16; o; o >>= 1) s += __shfl_xor_sync(0xffffffffu, s, o);
    if (lane == 0) sred[w] = s;
    __syncthreads();
    float bs = 0.f;
#pragma unroll
    for (int i = 0; i < 8; i++) bs += sred[i];
    float lse = bm + logf(bs);

    for (int t = tid; t < V_; t += 256) row[t] -= lse;
}

// ---------------- launch ----------------
extern "C" void kernel_launch(void* const* d_in, const int* in_sizes, int n_in,
                              void* d_out, int out_size) {
    const int*   input  = (const int*)d_in[0];
    const float* prev_h = (const float*)d_in[1];
    const float* prev_c = (const float*)d_in[2];
    const float* enc    = (const float*)d_in[3];
    const float* emb    = (const float*)d_in[4];
    const float* W_ih   = (const float*)d_in[5];
    const float* W_hh   = (const float*)d_in[6];
    const float* b_ih   = (const float*)d_in[7];
    const float* b_hh   = (const float*)d_in[8];
    const float* W_out  = (const float*)d_in[9];
    const float* b_out  = (const float*)d_in[10];
    const float* W_out2 = (const float*)d_in[11];
    const float* b_out2 = (const float*)d_in[12];
    float* out = (float*)d_out;

    float *xbuf, *gates, *avin, *av;
    cudaGetSymbolAddress((void**)&xbuf,  g_xbuf);
    cudaGetSymbolAddress((void**)&gates, g_gates);
    cudaGetSymbolAddress((void**)&avin,  g_avin);
    cudaGetSymbolAddress((void**)&av,    g_av);

    // 1) gather x = emb[input]
    gather_emb_kernel<<<(B_ * H_ / 4) / 256, 256>>>(input, emb);

    // 2) gates = [x | prev_h] @ [W_ih | W_hh]^T + b_ih + b_hh   (128 x 4096, K=2048)
    {
        dim3 grid(4 * H_ / 64, B_ / 64);
        sgemm_f32x2<64, 64, 2, 8, 0><<<grid, 256>>>(
            xbuf, prev_h, H_, W_ih, W_hh, H_, b_ih, b_hh,
            gates, 4 * H_, 2 * H_, H_);
    }

    // 3) LSTM elementwise -> h, c (into d_out) and h -> g_avin[:, H:]
    lstm_cell_kernel<<<(B_ * H_ + 255) / 256, 256>>>(prev_c, out);

    // 4) attention -> context into g_avin[:, :H]
    attention_kernel<<<B_, 256>>>(enc);

    // 5) attention_vector = tanh([ctx|h] @ W_out^T + b_out)  (128 x 1024, K=2048)
    {
        dim3 grid(A_ / 64, B_ / 32);
        sgemm_f32x2<32, 64, 1, 8, 1><<<grid, 256>>>(
            avin, avin, 2 * H_, W_out, W_out, 2 * H_, b_out, nullptr,
            av, A_, 2 * H_, 2 * H_);
    }

    // 6) logits = av @ W_out2^T + b_out2  (128 x 50000, K=1024) -> d_out directly
    {
        dim3 grid((V_ + 127) / 128, 1);
        sgemm_f32x2<128, 128, 8, 8, 0><<<grid, 256>>>(
            av, av, A_, W_out2, W_out2, A_, b_out2, nullptr,
            out, V_, A_, A_);
    }

    // 7) log_softmax in place over the [B, V] logits section
    log_softmax_kernel<<<B_, 256>>>(out);
}

// round 15
// speedup vs baseline: 1.0013x; 1.0013x over previous
#include <cuda_runtime.h>
#include <math.h>
#include <stdint.h>

// Problem dims
#define B_ 128
#define S_ 128
#define H_ 1024
#define A_ 1024
#define V_ 50000

// ---------------- scratch (device globals: allocation-free) ----------------
__device__ float g_xbuf[B_ * H_];        // gathered embeddings x = emb[input]
__device__ float g_gates[B_ * 4 * H_];   // LSTM pre-activations
__device__ float g_avin[B_ * 2 * H_];    // [context | h]
__device__ float g_av[B_ * A_];          // attention_vector (post tanh)

// ---------------- packed f32x2 helpers ----------------
__device__ __forceinline__ unsigned long long pack2(float lo, float hi) {
    unsigned long long r;
    unsigned int a = __float_as_uint(lo), b = __float_as_uint(hi);
    asm("mov.b64 %0, {%1,%2};" : "=l"(r) : "r"(a), "r"(b));
    return r;
}
__device__ __forceinline__ void unpack2(unsigned long long v, float& lo, float& hi) {
    unsigned int a, b;
    asm("mov.b64 {%0,%1}, %2;" : "=r"(a), "=r"(b) : "l"(v));
    lo = __uint_as_float(a);
    hi = __uint_as_float(b);
}
__device__ __forceinline__ void ffma2(unsigned long long& d, unsigned long long a,
                                      unsigned long long b) {
    asm("fma.rn.f32x2 %0, %1, %2, %0;" : "+l"(d) : "l"(a), "l"(b));
}

// ---------------- generic SGEMM: C[M,N] = A[M,K] @ B[N,K]^T + bias ----------------
// Dual-source along K (for the [x|prev_h] @ [W_ih|W_hh]^T fused gates GEMM):
// for k < Ksplit use (A1,B1) at offset k, else (A2,B2) at offset k-Ksplit.
// ACT: 0 = none, 1 = tanh.
template <int BM, int BN, int TM, int TN, int ACT>
__global__ void __launch_bounds__(256) sgemm_f32x2(
    const float* __restrict__ A1, const float* __restrict__ A2, int lda,
    const float* __restrict__ B1, const float* __restrict__ B2, int ldb,
    const float* __restrict__ bias1, const float* __restrict__ bias2,
    float* __restrict__ C, int N, int K, int Ksplit)
{
    constexpr int BK  = 32;
    constexpr int TNX = BN / TN;   // threads along N
    constexpr int TNY = BM / TM;   // threads along M
    static_assert(TNX * TNY == 256, "thread tiling must cover 256 threads");
    static_assert((TN % 2) == 0, "TN must be even for f32x2 pairing");
    constexpr int A4 = (BM * BK) / (256 * 4);
    constexpr int B4 = (BN * BK) / (256 * 4);
    static_assert((BM * BK) % 1024 == 0 && (BN * BK) % 1024 == 0, "tile loader");

    __shared__ float As[BK][BM];
    __shared__ float Bs[BK][BN];

    const int tid = threadIdx.x;
    const int tx  = tid % TNX;
    const int ty  = tid / TNX;
    const int n0  = blockIdx.x * BN;
    const int m0  = blockIdx.y * BM;

    unsigned long long acc[TM][TN / 2];
#pragma unroll
    for (int i = 0; i < TM; i++)
#pragma unroll
        for (int j = 0; j < TN / 2; j++) acc[i][j] = 0ull;

    for (int k0 = 0; k0 < K; k0 += BK) {
        const float* Asrc;
        const float* Bsrc;
        int kk;
        if (k0 < Ksplit) { Asrc = A1; Bsrc = B1; kk = k0; }
        else             { Asrc = A2; Bsrc = B2; kk = k0 - Ksplit; }

        // load A tile (BM x 32), transposed into As[k][m]; all M rows valid
#pragma unroll
        for (int r = 0; r < A4; r++) {
            int f   = tid + r * 256;
            int row = f >> 3;       // 8 float4 per 32-col row
            int cv  = f & 7;
            float4 v = *(const float4*)(Asrc + (long long)(m0 + row) * lda + kk + cv * 4);
            As[cv * 4 + 0][row] = v.x;
            As[cv * 4 + 1][row] = v.y;
            As[cv * 4 + 2][row] = v.z;
            As[cv * 4 + 3][row] = v.w;
        }
        // load B tile (BN x 32) with N guard
#pragma unroll
        for (int r = 0; r < B4; r++) {
            int f   = tid + r * 256;
            int row = f >> 3;
            int cv  = f & 7;
            int g   = n0 + row;
            float4 v;
            if (g < N) v = *(const float4*)(Bsrc + (long long)g * ldb + kk + cv * 4);
            else       v = make_float4(0.f, 0.f, 0.f, 0.f);
            Bs[cv * 4 + 0][row] = v.x;
            Bs[cv * 4 + 1][row] = v.y;
            Bs[cv * 4 + 2][row] = v.z;
            Bs[cv * 4 + 3][row] = v.w;
        }
        __syncthreads();

#pragma unroll
        for (int k = 0; k < BK; k++) {
            float a[TM];
#pragma unroll
            for (int i = 0; i < TM; i++) a[i] = As[k][ty * TM + i];
            unsigned long long bp[TN / 2];
#pragma unroll
            for (int j = 0; j < TN / 2; j++)
                bp[j] = *(const unsigned long long*)&Bs[k][tx * TN + 2 * j];
#pragma unroll
            for (int i = 0; i < TM; i++) {
                unsigned long long ap = pack2(a[i], a[i]);
#pragma unroll
                for (int j = 0; j < TN / 2; j++) ffma2(acc[i][j], ap, bp[j]);
            }
        }
        __syncthreads();
    }

    // epilogue
#pragma unroll
    for (int i = 0; i < TM; i++) {
        int m = m0 + ty * TM + i;
#pragma unroll
        for (int j = 0; j < TN / 2; j++) {
            float c0, c1;
            unpack2(acc[i][j], c0, c1);
            int col = n0 + tx * TN + 2 * j;
            if (col < N) {
                float bb = bias1 ? bias1[col] : 0.f;
                if (bias2) bb += bias2[col];
                float v = c0 + bb;
                if (ACT == 1) v = tanhf(v);
                C[(long long)m * N + col] = v;
            }
            if (col + 1 < N) {
                float bb = bias1 ? bias1[col + 1] : 0.f;
                if (bias2) bb += bias2[col + 1];
                float v = c1 + bb;
                if (ACT == 1) v = tanhf(v);
                C[(long long)m * N + col + 1] = v;
            }
        }
    }
}

// ---------------- embedding gather: g_xbuf[b, :] = emb[input[b], :] ----------------
__global__ void gather_emb_kernel(const int* __restrict__ input,
                                  const float* __restrict__ emb) {
    int idx = blockIdx.x * blockDim.x + threadIdx.x;  // float4 index
    int b   = idx >> 8;                               // H_/4 = 256 float4/row
    int k4  = idx & 255;
    ((float4*)g_xbuf)[idx] =
        ((const float4*)(emb + (long long)input[b] * H_))[k4];
}

// ---------------- LSTM elementwise: c, h from gates ----------------
__global__ void lstm_cell_kernel(const float* __restrict__ prev_c,
                                 float* __restrict__ out) {
    int idx = blockIdx.x * blockDim.x + threadIdx.x;
    if (idx >= B_ * H_) return;
    int b = idx >> 10;
    int j = idx & 1023;
    const float* g = g_gates + b * (4 * H_);
    float ig = g[j];
    float fg = g[H_ + j];
    float gg = g[2 * H_ + j];
    float og = g[3 * H_ + j];
    float si = 1.f / (1.f + expf(-ig));
    float sf = 1.f / (1.f + expf(-fg));
    float so = 1.f / (1.f + expf(-og));
    float c  = sf * prev_c[idx] + si * tanhf(gg);
    float h  = so * tanhf(c);
    out[(long long)B_ * V_ + idx] = h;                 // h output section
    out[(long long)B_ * V_ + B_ * H_ + idx] = c;       // c output section
    g_avin[b * (2 * H_) + H_ + j] = h;                 // second half of [ctx|h]
}

// ---------------- dot attention + softmax + context (one block per batch) ----------
__global__ void __launch_bounds__(256) attention_kernel(const float* __restrict__ enc) {
    int b = blockIdx.x;
    __shared__ float sh[H_];
    __shared__ float sc[S_];
    __shared__ float sinv;
    int tid  = threadIdx.x;
    int lane = tid & 31;
    int w    = tid >> 5;

    for (int t = tid; t < H_; t += 256) sh[t] = g_avin[b * (2 * H_) + H_ + t];
    __syncthreads();

    const float* eb = enc + (long long)b * S_ * H_;
    for (int s = w; s < S_; s += 8) {
        const float* e = eb + s * H_;
        float a0 = 0.f, a1 = 0.f;
#pragma unroll 4
        for (int t = lane; t < H_; t += 64) {
            a0 += e[t] * sh[t];
            a1 += e[t + 32] * sh[t + 32];
        }
        float acc = a0 + a1;
#pragma unroll
        for (int o = 16; o; o >>= 1) acc += __shfl_xor_sync(0xffffffffu, acc, o);
        if (lane == 0) sc[s] = (acc == 0.f) ? -1e11f : acc;
    }
    __syncthreads();

    if (w == 0) {
        float v0 = sc[lane], v1 = sc[lane + 32], v2 = sc[lane + 64], v3 = sc[lane + 96];
        float m = fmaxf(fmaxf(v0, v1), fmaxf(v2, v3));
#pragma unroll
        for (int o = 16; o; o >>= 1) m = fmaxf(m, __shfl_xor_sync(0xffffffffu, m, o));
        float e0 = expf(v0 - m), e1 = expf(v1 - m), e2 = expf(v2 - m), e3 = expf(v3 - m);
        sc[lane] = e0; sc[lane + 32] = e1; sc[lane + 64] = e2; sc[lane + 96] = e3;
        float s4 = e0 + e1 + e2 + e3;
#pragma unroll
        for (int o = 16; o; o >>= 1) s4 += __shfl_xor_sync(0xffffffffu, s4, o);
        if (lane == 0) sinv = 1.f / s4;
    }
    __syncthreads();

    float inv = sinv;
    float acc0 = 0.f, acc1 = 0.f, acc2 = 0.f, acc3 = 0.f;
#pragma unroll 4
    for (int s = 0; s < S_; s++) {
        float a = sc[s];
        const float* e = eb + s * H_ + tid;
        acc0 += a * e[0];
        acc1 += a * e[256];
        acc2 += a * e[512];
        acc3 += a * e[768];
    }
    g_avin[b * (2 * H_) + tid]       = acc0 * inv;
    g_avin[b * (2 * H_) + tid + 256] = acc1 * inv;
    g_avin[b * (2 * H_) + tid + 512] = acc2 * inv;
    g_avin[b * (2 * H_) + tid + 768] = acc3 * inv;
}

// ---------------- log_softmax over V, in place (one block per row) ----------------
__global__ void __launch_bounds__(256) log_softmax_kernel(float* __restrict__ out) {
    int b = blockIdx.x;
    float* row = out + (long long)b * V_;
    __shared__ float sred[8];
    int tid  = threadIdx.x;
    int lane = tid & 31;
    int w    = tid >> 5;

    float m = -INFINITY;
    for (int t = tid; t < V_; t += 256) m = fmaxf(m, row[t]);
#pragma unroll
    for (int o = 16; o; o >>= 1) m = fmaxf(m, __shfl_xor_sync(0xffffffffu, m, o));
    if (lane == 0) sred[w] = m;
    __syncthreads();
    float bm = sred[0];
#pragma unroll
    for (int i = 1; i < 8; i++) bm = fmaxf(bm, sred[i]);
    __syncthreads();

    float s = 0.f;
    for (int t = tid; t < V_; t += 256) s += expf(row[t] - bm);
#pragma unroll
    for (int o = 16; o; o >>= 1) s += __shfl_xor_sync(0xffffffffu, s, o);
    if (lane == 0) sred[w] = s;
    __syncthreads();
    float bs = 0.f;
#pragma unroll
    for (int i = 0; i < 8; i++) bs += sred[i];
    float lse = bm + logf(bs);

    for (int t = tid; t < V_; t += 256) row[t] -= lse;
}

// ---------------- launch ----------------
extern "C" void kernel_launch(void* const* d_in, const int* in_sizes, int n_in,
                              void* d_out, int out_size) {
    const int*   input  = (const int*)d_in[0];
    const float* prev_h = (const float*)d_in[1];
    const float* prev_c = (const float*)d_in[2];
    const float* enc    = (const float*)d_in[3];
    const float* emb    = (const float*)d_in[4];
    const float* W_ih   = (const float*)d_in[5];
    const float* W_hh   = (const float*)d_in[6];
    const float* b_ih   = (const float*)d_in[7];
    const float* b_hh   = (const float*)d_in[8];
    const float* W_out  = (const float*)d_in[9];
    const float* b_out  = (const float*)d_in[10];
    const float* W_out2 = (const float*)d_in[11];
    const float* b_out2 = (const float*)d_in[12];
    float* out = (float*)d_out;

    float *xbuf, *gates, *avin, *av;
    cudaGetSymbolAddress((void**)&xbuf,  g_xbuf);
    cudaGetSymbolAddress((void**)&gates, g_gates);
    cudaGetSymbolAddress((void**)&avin,  g_avin);
    cudaGetSymbolAddress((void**)&av,    g_av);

    // 1) gather x = emb[input]
    gather_emb_kernel<<<(B_ * H_ / 4) / 256, 256>>>(input, emb);

    // 2) gates = [x | prev_h] @ [W_ih | W_hh]^T + b_ih + b_hh   (128 x 4096, K=2048)
    {
        dim3 grid(4 * H_ / 64, B_ / 64);
        sgemm_f32x2<64, 64, 2, 8, 0><<<grid, 256>>>(
            xbuf, prev_h, H_, W_ih, W_hh, H_, b_ih, b_hh,
            gates, 4 * H_, 2 * H_, H_);
    }

    // 3) LSTM elementwise -> h, c (into d_out) and h -> g_avin[:, H:]
    lstm_cell_kernel<<<(B_ * H_ + 255) / 256, 256>>>(prev_c, out);

    // 4) attention -> context into g_avin[:, :H]
    attention_kernel<<<B_, 256>>>(enc);

    // 5) attention_vector = tanh([ctx|h] @ W_out^T + b_out)  (128 x 1024, K=2048)
    {
        dim3 grid(A_ / 64, B_ / 32);
        sgemm_f32x2<32, 64, 1, 8, 1><<<grid, 256>>>(
            avin, avin, 2 * H_, W_out, W_out, 2 * H_, b_out, nullptr,
            av, A_, 2 * H_, 2 * H_);
    }

    // 6) logits = av @ W_out2^T + b_out2  (128 x 50000, K=1024) -> d_out directly
    {
        dim3 grid((V_ + 127) / 128, 1);
        sgemm_f32x2<128, 128, 8, 8, 0><<<grid, 256>>>(
            av, av, A_, W_out2, W_out2, A_, b_out2, nullptr,
            out, V_, A_, A_);
    }

    // 7) log_softmax in place over the [B, V] logits section
    log_softmax_kernel<<<B_, 256>>>(out);
}

// round 16
// speedup vs baseline: 1.0014x; 1.0000x over previous
#include <cuda_runtime.h>
#include <math.h>
#include <stdint.h>

// Problem dims
#define B_ 128
#define S_ 128
#define H_ 1024
#define A_ 1024
#define V_ 50000

// ---------------- scratch (device globals: allocation-free) ----------------
__device__ float g_xbuf[B_ * H_];        // gathered embeddings x = emb[input]
__device__ float g_gates[B_ * 4 * H_];   // LSTM pre-activations
__device__ float g_avin[B_ * 2 * H_];    // [context | h]
__device__ float g_av[B_ * A_];          // attention_vector (post tanh)

// ---------------- packed f32x2 helpers ----------------
__device__ __forceinline__ unsigned long long pack2(float lo, float hi) {
    unsigned long long r;
    unsigned int a = __float_as_uint(lo), b = __float_as_uint(hi);
    asm("mov.b64 %0, {%1,%2};" : "=l"(r) : "r"(a), "r"(b));
    return r;
}
__device__ __forceinline__ void unpack2(unsigned long long v, float& lo, float& hi) {
    unsigned int a, b;
    asm("mov.b64 {%0,%1}, %2;" : "=r"(a), "=r"(b) : "l"(v));
    lo = __uint_as_float(a);
    hi = __uint_as_float(b);
}
__device__ __forceinline__ void ffma2(unsigned long long& d, unsigned long long a,
                                      unsigned long long b) {
    asm("fma.rn.f32x2 %0, %1, %2, %0;" : "+l"(d) : "l"(a), "l"(b));
}

// ---------------- generic SGEMM: C[M,N] = A[M,K] @ B[N,K]^T + bias ----------------
// Dual-source along K (for the [x|prev_h] @ [W_ih|W_hh]^T fused gates GEMM):
// for k < Ksplit use (A1,B1) at offset k, else (A2,B2) at offset k-Ksplit.
// ACT: 0 = none, 1 = tanh.
template <int BM, int BN, int TM, int TN, int ACT>
__global__ void __launch_bounds__(256) sgemm_f32x2(
    const float* __restrict__ A1, const float* __restrict__ A2, int lda,
    const float* __restrict__ B1, const float* __restrict__ B2, int ldb,
    const float* __restrict__ bias1, const float* __restrict__ bias2,
    float* __restrict__ C, int N, int K, int Ksplit)
{
    constexpr int BK  = 32;
    constexpr int TNX = BN / TN;   // threads along N
    constexpr int TNY = BM / TM;   // threads along M
    static_assert(TNX * TNY == 256, "thread tiling must cover 256 threads");
    static_assert((TN % 2) == 0, "TN must be even for f32x2 pairing");
    constexpr int A4 = (BM * BK) / (256 * 4);
    constexpr int B4 = (BN * BK) / (256 * 4);
    static_assert((BM * BK) % 1024 == 0 && (BN * BK) % 1024 == 0, "tile loader");

    __shared__ float As[BK][BM];
    __shared__ float Bs[BK][BN];

    const int tid = threadIdx.x;
    const int tx  = tid % TNX;
    const int ty  = tid / TNX;
    const int n0  = blockIdx.x * BN;
    const int m0  = blockIdx.y * BM;

    unsigned long long acc[TM][TN / 2];
#pragma unroll
    for (int i = 0; i < TM; i++)
#pragma unroll
        for (int j = 0; j < TN / 2; j++) acc[i][j] = 0ull;

    for (int k0 = 0; k0 < K; k0 += BK) {
        const float* Asrc;
        const float* Bsrc;
        int kk;
        if (k0 < Ksplit) { Asrc = A1; Bsrc = B1; kk = k0; }
        else             { Asrc = A2; Bsrc = B2; kk = k0 - Ksplit; }

        // load A tile (BM x 32), transposed into As[k][m]; all M rows valid
#pragma unroll
        for (int r = 0; r < A4; r++) {
            int f   = tid + r * 256;
            int row = f >> 3;       // 8 float4 per 32-col row
            int cv  = f & 7;
            float4 v = *(const float4*)(Asrc + (long long)(m0 + row) * lda + kk + cv * 4);
            As[cv * 4 + 0][row] = v.x;
            As[cv * 4 + 1][row] = v.y;
            As[cv * 4 + 2][row] = v.z;
            As[cv * 4 + 3][row] = v.w;
        }
        // load B tile (BN x 32) with N guard
#pragma unroll
        for (int r = 0; r < B4; r++) {
            int f   = tid + r * 256;
            int row = f >> 3;
            int cv  = f & 7;
            int g   = n0 + row;
            float4 v;
            if (g < N) v = *(const float4*)(Bsrc + (long long)g * ldb + kk + cv * 4);
            else       v = make_float4(0.f, 0.f, 0.f, 0.f);
            Bs[cv * 4 + 0][row] = v.x;
            Bs[cv * 4 + 1][row] = v.y;
            Bs[cv * 4 + 2][row] = v.z;
            Bs[cv * 4 + 3][row] = v.w;
        }
        __syncthreads();

#pragma unroll
        for (int k = 0; k < BK; k++) {
            float a[TM];
#pragma unroll
            for (int i = 0; i < TM; i++) a[i] = As[k][ty * TM + i];
            unsigned long long bp[TN / 2];
#pragma unroll
            for (int j = 0; j < TN / 2; j++)
                bp[j] = *(const unsigned long long*)&Bs[k][tx * TN + 2 * j];
#pragma unroll
            for (int i = 0; i < TM; i++) {
                unsigned long long ap = pack2(a[i], a[i]);
#pragma unroll
                for (int j = 0; j < TN / 2; j++) ffma2(acc[i][j], ap, bp[j]);
            }
        }
        __syncthreads();
    }

    // epilogue
#pragma unroll
    for (int i = 0; i < TM; i++) {
        int m = m0 + ty * TM + i;
#pragma unroll
        for (int j = 0; j < TN / 2; j++) {
            float c0, c1;
            unpack2(acc[i][j], c0, c1);
            int col = n0 + tx * TN + 2 * j;
            if (col < N) {
                float bb = bias1 ? bias1[col] : 0.f;
                if (bias2) bb += bias2[col];
                float v = c0 + bb;
                if (ACT == 1) v = tanhf(v);
                C[(long long)m * N + col] = v;
            }
            if (col + 1 < N) {
                float bb = bias1 ? bias1[col + 1] : 0.f;
                if (bias2) bb += bias2[col + 1];
                float v = c1 + bb;
                if (ACT == 1) v = tanhf(v);
                C[(long long)m * N + col + 1] = v;
            }
        }
    }
}

// ---------------- embedding gather: g_xbuf[b, :] = emb[input[b], :] ----------------
__global__ void gather_emb_kernel(const int* __restrict__ input,
                                  const float* __restrict__ emb) {
    int idx = blockIdx.x * blockDim.x + threadIdx.x;  // float4 index
    int b   = idx >> 8;                               // H_/4 = 256 float4/row
    int k4  = idx & 255;
    ((float4*)g_xbuf)[idx] =
        ((const float4*)(emb + (long long)input[b] * H_))[k4];
}

// ---------------- LSTM elementwise: c, h from gates ----------------
__global__ void lstm_cell_kernel(const float* __restrict__ prev_c,
                                 float* __restrict__ out) {
    int idx = blockIdx.x * blockDim.x + threadIdx.x;
    if (idx >= B_ * H_) return;
    int b = idx >> 10;
    int j = idx & 1023;
    const float* g = g_gates + b * (4 * H_);
    float ig = g[j];
    float fg = g[H_ + j];
    float gg = g[2 * H_ + j];
    float og = g[3 * H_ + j];
    float si = 1.f / (1.f + expf(-ig));
    float sf = 1.f / (1.f + expf(-fg));
    float so = 1.f / (1.f + expf(-og));
    float c  = sf * prev_c[idx] + si * tanhf(gg);
    float h  = so * tanhf(c);
    out[(long long)B_ * V_ + idx] = h;                 // h output section
    out[(long long)B_ * V_ + B_ * H_ + idx] = c;       // c output section
    g_avin[b * (2 * H_) + H_ + j] = h;                 // second half of [ctx|h]
}

// ---------------- dot attention + softmax + context (one block per batch) ----------
__global__ void __launch_bounds__(256) attention_kernel(const float* __restrict__ enc) {
    int b = blockIdx.x;
    __shared__ float sh[H_];
    __shared__ float sc[S_];
    __shared__ float sinv;
    int tid  = threadIdx.x;
    int lane = tid & 31;
    int w    = tid >> 5;

    for (int t = tid; t < H_; t += 256) sh[t] = g_avin[b * (2 * H_) + H_ + t];
    __syncthreads();

    const float* eb = enc + (long long)b * S_ * H_;
    for (int s = w; s < S_; s += 8) {
        const float* e = eb + s * H_;
        float a0 = 0.f, a1 = 0.f;
#pragma unroll 4
        for (int t = lane; t < H_; t += 64) {
            a0 += e[t] * sh[t];
            a1 += e[t + 32] * sh[t + 32];
        }
        float acc = a0 + a1;
#pragma unroll
        for (int o = 16; o; o >>= 1) acc += __shfl_xor_sync(0xffffffffu, acc, o);
        if (lane == 0) sc[s] = (acc == 0.f) ? -1e11f : acc;
    }
    __syncthreads();

    if (w == 0) {
        float v0 = sc[lane], v1 = sc[lane + 32], v2 = sc[lane + 64], v3 = sc[lane + 96];
        float m = fmaxf(fmaxf(v0, v1), fmaxf(v2, v3));
#pragma unroll
        for (int o = 16; o; o >>= 1) m = fmaxf(m, __shfl_xor_sync(0xffffffffu, m, o));
        float e0 = expf(v0 - m), e1 = expf(v1 - m), e2 = expf(v2 - m), e3 = expf(v3 - m);
        sc[lane] = e0; sc[lane + 32] = e1; sc[lane + 64] = e2; sc[lane + 96] = e3;
        float s4 = e0 + e1 + e2 + e3;
#pragma unroll
        for (int o = 16; o; o >>= 1) s4 += __shfl_xor_sync(0xffffffffu, s4, o);
        if (lane == 0) sinv = 1.f / s4;
    }
    __syncthreads();

    float inv = sinv;
    float acc0 = 0.f, acc1 = 0.f, acc2 = 0.f, acc3 = 0.f;
#pragma unroll 4
    for (int s = 0; s < S_; s++) {
        float a = sc[s];
        const float* e = eb + s * H_ + tid;
        acc0 += a * e[0];
        acc1 += a * e[256];
        acc2 += a * e[512];
        acc3 += a * e[768];
    }
    g_avin[b * (2 * H_) + tid]       = acc0 * inv;
    g_avin[b * (2 * H_) + tid + 256] = acc1 * inv;
    g_avin[b * (2 * H_) + tid + 512] = acc2 * inv;
    g_avin[b * (2 * H_) + tid + 768] = acc3 * inv;
}

// ---------------- log_softmax over V, in place (one block per row) ----------------
__global__ void __launch_bounds__(256) log_softmax_kernel(float* __restrict__ out) {
    int b = blockIdx.x;
    float* row = out + (long long)b * V_;
    __shared__ float sred[8];
    int tid  = threadIdx.x;
    int lane = tid & 31;
    int w    = tid >> 5;

    float m = -INFINITY;
    for (int t = tid; t < V_; t += 256) m = fmaxf(m, row[t]);
#pragma unroll
    for (int o = 16; o; o >>= 1) m = fmaxf(m, __shfl_xor_sync(0xffffffffu, m, o));
    if (lane == 0) sred[w] = m;
    __syncthreads();
    float bm = sred[0];
#pragma unroll
    for (int i = 1; i < 8; i++) bm = fmaxf(bm, sred[i]);
    __syncthreads();

    float s = 0.f;
    for (int t = tid; t < V_; t += 256) s += expf(row[t] - bm);
#pragma unroll
    for (int o = 16; o; o >>= 1) s += __shfl_xor_sync(0xffffffffu, s, o);
    if (lane == 0) sred[w] = s;
    __syncthreads();
    float bs = 0.f;
#pragma unroll
    for (int i = 0; i < 8; i++) bs += sred[i];
    float lse = bm + logf(bs);

    for (int t = tid; t < V_; t += 256) row[t] -= lse;
}

// ---------------- launch ----------------
extern "C" void kernel_launch(void* const* d_in, const int* in_sizes, int n_in,
                              void* d_out, int out_size) {
    const int*   input  = (const int*)d_in[0];
    const float* prev_h = (const float*)d_in[1];
    const float* prev_c = (const float*)d_in[2];
    const float* enc    = (const float*)d_in[3];
    const float* emb    = (const float*)d_in[4];
    const float* W_ih   = (const float*)d_in[5];
    const float* W_hh   = (const float*)d_in[6];
    const float* b_ih   = (const float*)d_in[7];
    const float* b_hh   = (const float*)d_in[8];
    const float* W_out  = (const float*)d_in[9];
    const float* b_out  = (const float*)d_in[10];
    const float* W_out2 = (const float*)d_in[11];
    const float* b_out2 = (const float*)d_in[12];
    float* out = (float*)d_out;

    float *xbuf, *gates, *avin, *av;
    cudaGetSymbolAddress((void**)&xbuf,  g_xbuf);
    cudaGetSymbolAddress((void**)&gates, g_gates);
    cudaGetSymbolAddress((void**)&avin,  g_avin);
    cudaGetSymbolAddress((void**)&av,    g_av);

    // 1) gather x = emb[input]
    gather_emb_kernel<<<(B_ * H_ / 4) / 256, 256>>>(input, emb);

    // 2) gates = [x | prev_h] @ [W_ih | W_hh]^T + b_ih + b_hh   (128 x 4096, K=2048)
    {
        dim3 grid(4 * H_ / 64, B_ / 64);
        sgemm_f32x2<64, 64, 2, 8, 0><<<grid, 256>>>(
            xbuf, prev_h, H_, W_ih, W_hh, H_, b_ih, b_hh,
            gates, 4 * H_, 2 * H_, H_);
    }

    // 3) LSTM elementwise -> h, c (into d_out) and h -> g_avin[:, H:]
    lstm_cell_kernel<<<(B_ * H_ + 255) / 256, 256>>>(prev_c, out);

    // 4) attention -> context into g_avin[:, :H]
    attention_kernel<<<B_, 256>>>(enc);

    // 5) attention_vector = tanh([ctx|h] @ W_out^T + b_out)  (128 x 1024, K=2048)
    {
        dim3 grid(A_ / 64, B_ / 32);
        sgemm_f32x2<32, 64, 1, 8, 1><<<grid, 256>>>(
            avin, avin, 2 * H_, W_out, W_out, 2 * H_, b_out, nullptr,
            av, A_, 2 * H_, 2 * H_);
    }

    // 6) logits = av @ W_out2^T + b_out2  (128 x 50000, K=1024) -> d_out directly
    {
        dim3 grid((V_ + 127) / 128, 1);
        sgemm_f32x2<128, 128, 8, 8, 0><<<grid, 256>>>(
            av, av, A_, W_out2, W_out2, A_, b_out2, nullptr,
            out, V_, A_, A_);
    }

    // 7) log_softmax in place over the [B, V] logits section
    log_softmax_kernel<<<B_, 256>>>(out);
}